// round 15
// baseline (speedup 1.0000x reference)
#include <cuda_runtime.h>
#include <cuda_bf16.h>
#include <math.h>
#include <stdint.h>

#define M_ROWS 36928   // B*T = 64*577
#define E_DIM  768
#define H_DIM  64
#define T_LEN  577
#define B_SZ   64
#define GW     24
#define TPAD   640     // padded T for transposed V

// scratch (static device arrays; no allocation)
__device__ float g_q[M_ROWS * H_DIM];
__device__ __nv_bfloat16 g_k_hi[(M_ROWS + 64) * H_DIM];
__device__ __nv_bfloat16 g_k_lo[(M_ROWS + 64) * H_DIM];
__device__ __nv_bfloat16 g_vT_hi[B_SZ * H_DIM * TPAD];
__device__ __nv_bfloat16 g_vT_lo[B_SZ * H_DIM * TPAD];
__device__ __nv_bfloat16 g_wcat_hi[192 * E_DIM];
__device__ __nv_bfloat16 g_wcat_lo[192 * E_DIM];

__device__ __forceinline__ uint32_t smem_u32(const void* p) {
    uint32_t a;
    asm("{ .reg .u64 t; cvta.to.shared.u64 t, %1; cvt.u32.u64 %0, t; }" : "=r"(a) : "l"(p));
    return a;
}
__device__ __forceinline__ void ldsm_x4(uint32_t* r, uint32_t addr) {
    asm volatile("ldmatrix.sync.aligned.m8n8.x4.shared.b16 {%0,%1,%2,%3}, [%4];"
                 : "=r"(r[0]), "=r"(r[1]), "=r"(r[2]), "=r"(r[3]) : "r"(addr));
}
__device__ __forceinline__ void mma_bf16(float* d, const uint32_t* a, const uint32_t* b) {
    asm volatile(
        "mma.sync.aligned.m16n8k16.row.col.f32.bf16.bf16.f32 "
        "{%0,%1,%2,%3}, {%4,%5,%6,%7}, {%8,%9}, {%0,%1,%2,%3};"
        : "+f"(d[0]), "+f"(d[1]), "+f"(d[2]), "+f"(d[3])
        : "r"(a[0]), "r"(a[1]), "r"(a[2]), "r"(a[3]), "r"(b[0]), "r"(b[1]));
}
__device__ __forceinline__ uint32_t packbf(__nv_bfloat16 a, __nv_bfloat16 b) {
    uint16_t ua = *(uint16_t*)&a, ub = *(uint16_t*)&b;
    return (uint32_t)ua | ((uint32_t)ub << 16);
}
__device__ __forceinline__ uint32_t pk_bf2(float lo, float hi) {
    uint32_t r; asm("cvt.rn.bf16x2.f32 %0, %1, %2;" : "=r"(r) : "f"(hi), "f"(lo)); return r;
}
__device__ __forceinline__ void cp16(uint32_t saddr, const void* gaddr) {
    asm volatile("cp.async.ca.shared.global [%0], [%1], 16;" :: "r"(saddr), "l"(gaddr) : "memory");
}
#define CP_COMMIT() asm volatile("cp.async.commit_group;" ::: "memory")
#define CP_WAIT1()  asm volatile("cp.async.wait_group 1;" ::: "memory")
#define CP_WAIT0()  asm volatile("cp.async.wait_group 0;" ::: "memory")

// ---------------------------------------------------------------------------
// Kernel 0a: weight prep
// ---------------------------------------------------------------------------
__global__ void prep_w_kernel(const float* __restrict__ w_q, const float* __restrict__ w_k,
                              const float* __restrict__ w_v)
{
    int idx = blockIdx.x * blockDim.x + threadIdx.x;
    if (idx >= 192 * E_DIM) return;
    int n = idx / E_DIM, k = idx % E_DIM;
    const float* w = (n < 64) ? w_q : (n < 128) ? w_k : w_v;
    float v = w[k * H_DIM + (n & 63)];
    __nv_bfloat16 hi = __float2bfloat16(v);
    __nv_bfloat16 lo = __float2bfloat16(v - __bfloat162float(hi));
    g_wcat_hi[idx] = hi;
    g_wcat_lo[idx] = lo;
}

// ---------------------------------------------------------------------------
// Kernel 0b: zero padding regions
// ---------------------------------------------------------------------------
__global__ void pad_kernel()
{
    int idx = blockIdx.x * blockDim.x + threadIdx.x;
    const __nv_bfloat16 z = __float2bfloat16(0.f);
    if (idx < 64 * H_DIM) {
        g_k_hi[(size_t)M_ROWS * H_DIM + idx] = z;
        g_k_lo[(size_t)M_ROWS * H_DIM + idx] = z;
    }
    const int NPAD = TPAD - T_LEN;
    const int NV = B_SZ * H_DIM * NPAD;
    if (idx < NV) {
        int b = idx / (H_DIM * NPAD);
        int rem = idx % (H_DIM * NPAD);
        int h = rem / NPAD;
        int j = rem % NPAD;
        size_t pos = ((size_t)(b * H_DIM + h)) * TPAD + T_LEN + j;
        g_vT_hi[pos] = z;
        g_vT_lo[pos] = z;
    }
}

// ---------------------------------------------------------------------------
// Kernel 1: split-bf16 mma.sync QKV GEMM + LayerNorm (R13, unchanged)
// ---------------------------------------------------------------------------
#define GK 64
#define NCHUNK (E_DIM / GK)
#define AS 144
#define A_LO_OFF 9216
#define ABUF(i) ((i) * 18432)
#define B_LO_OFF 27648
#define BBUF(i) (36864 + (i) * 55296)
#define SM_TOTAL (36864 + 2 * 55296)
#define STG_S 201

__device__ __forceinline__ void qkv_store_A(char* smc, int tid, const float4* av, uint32_t abuf)
{
#pragma unroll
    for (int it = 0; it < 4; it++) {
        int i = tid + it * 256;
        int r = i >> 4, col = (i & 15) * 4;
        float4 v = av[it];
        __nv_bfloat16 h0 = __float2bfloat16(v.x), h1 = __float2bfloat16(v.y);
        __nv_bfloat16 h2 = __float2bfloat16(v.z), h3 = __float2bfloat16(v.w);
        __nv_bfloat16 l0 = __float2bfloat16(v.x - __bfloat162float(h0));
        __nv_bfloat16 l1 = __float2bfloat16(v.y - __bfloat162float(h1));
        __nv_bfloat16 l2 = __float2bfloat16(v.z - __bfloat162float(h2));
        __nv_bfloat16 l3 = __float2bfloat16(v.w - __bfloat162float(h3));
        uint32_t off = abuf + (uint32_t)(r * AS + col * 2);
        *(uint2*)(smc + off)            = make_uint2(packbf(h0, h1), packbf(h2, h3));
        *(uint2*)(smc + off + A_LO_OFF) = make_uint2(packbf(l0, l1), packbf(l2, l3));
    }
}
__device__ __forceinline__ void qkv_cp_B(uint32_t sb, int tid, int k0, uint32_t bbuf)
{
#pragma unroll
    for (int it = 0; it < 6; it++) {
        int i = tid + it * 256;
        int r = i >> 3, seg = i & 7;
        uint32_t soff = sb + bbuf + (uint32_t)(r * AS + seg * 16);
        size_t goff = (size_t)r * E_DIM + k0 + seg * 8;
        cp16(soff,            g_wcat_hi + goff);
        cp16(soff + B_LO_OFF, g_wcat_lo + goff);
    }
}

__global__ __launch_bounds__(256) void qkv_mma_kernel(
    const float* __restrict__ x,
    const float* __restrict__ q_gamma, const float* __restrict__ q_beta,
    const float* __restrict__ k_gamma, const float* __restrict__ k_beta)
{
    extern __shared__ char smc[];
    const uint32_t sb = smem_u32(smc);
    const int tid  = threadIdx.x;
    const int wid  = tid >> 5;
    const int lane = tid & 31;
    const int wm   = wid >> 2;
    const int wn   = wid & 3;
    const int m0   = blockIdx.x * 64;

    const uint32_t aOff = (uint32_t)((wm * 32 + (lane & 15)) * AS + (lane >> 4) * 16);
    const uint32_t bOff = (uint32_t)((wn * 48 + ((lane >> 4) << 3) + (lane & 7)) * AS
                                     + ((lane >> 3) & 1) * 16);

    float acc[2][6][4];
#pragma unroll
    for (int i = 0; i < 2; i++)
#pragma unroll
        for (int j = 0; j < 6; j++)
#pragma unroll
            for (int c = 0; c < 4; c++) acc[i][j][c] = 0.f;

    float4 av[4];
    qkv_cp_B(sb, tid, 0, BBUF(0));
    CP_COMMIT();
#pragma unroll
    for (int it = 0; it < 4; it++) {
        int i = tid + it * 256;
        int r = i >> 4, col = (i & 15) * 4;
        av[it] = *(const float4*)&x[(size_t)(m0 + r) * E_DIM + 0 + col];
    }
    qkv_store_A(smc, tid, av, ABUF(0));
    qkv_cp_B(sb, tid, GK, BBUF(1));
    CP_COMMIT();
#pragma unroll
    for (int it = 0; it < 4; it++) {
        int i = tid + it * 256;
        int r = i >> 4, col = (i & 15) * 4;
        av[it] = *(const float4*)&x[(size_t)(m0 + r) * E_DIM + GK + col];
    }

    for (int ch = 0; ch < NCHUNK; ch++) {
        const int cur = ch & 1;
        if (ch < NCHUNK - 1) CP_WAIT1(); else CP_WAIT0();
        __syncthreads();

        const uint32_t aHi = sb + ABUF(cur) + aOff;
        const uint32_t bHi = sb + BBUF(cur) + bOff;
#pragma unroll
        for (int ks = 0; ks < 4; ks++) {
            const uint32_t kb = (uint32_t)(ks * 32);
            uint32_t ahi[2][4], alo[2][4];
#pragma unroll
            for (int im = 0; im < 2; im++) {
                ldsm_x4(ahi[im], aHi + im * 16 * AS + kb);
                ldsm_x4(alo[im], aHi + A_LO_OFF + im * 16 * AS + kb);
            }
            uint32_t bhi[6][2], blo[6][2];
#pragma unroll
            for (int j = 0; j < 3; j++) {
                uint32_t t[4];
                ldsm_x4(t, bHi + j * 16 * AS + kb);
                bhi[2 * j][0] = t[0]; bhi[2 * j][1] = t[1];
                bhi[2 * j + 1][0] = t[2]; bhi[2 * j + 1][1] = t[3];
                ldsm_x4(t, bHi + B_LO_OFF + j * 16 * AS + kb);
                blo[2 * j][0] = t[0]; blo[2 * j][1] = t[1];
                blo[2 * j + 1][0] = t[2]; blo[2 * j + 1][1] = t[3];
            }
#pragma unroll
            for (int im = 0; im < 2; im++)
#pragma unroll
                for (int jn = 0; jn < 6; jn++) {
                    mma_bf16(acc[im][jn], ahi[im], bhi[jn]);
                    mma_bf16(acc[im][jn], ahi[im], blo[jn]);
                    mma_bf16(acc[im][jn], alo[im], bhi[jn]);
                }
        }

        if (ch < NCHUNK - 1)
            qkv_store_A(smc, tid, av, ABUF((ch + 1) & 1));
        __syncthreads();

        if (ch < NCHUNK - 2) {
            const int k0n = (ch + 2) * GK;
            qkv_cp_B(sb, tid, k0n, BBUF(cur));
            CP_COMMIT();
#pragma unroll
            for (int it = 0; it < 4; it++) {
                int i = tid + it * 256;
                int r = i >> 4, col = (i & 15) * 4;
                av[it] = *(const float4*)&x[(size_t)(m0 + r) * E_DIM + k0n + col];
            }
        }
    }
    __syncthreads();

    float* stage = (float*)smc;
#pragma unroll
    for (int im = 0; im < 2; im++)
#pragma unroll
        for (int jn = 0; jn < 6; jn++) {
            int row = wm * 32 + im * 16 + (lane >> 2);
            int col = wn * 48 + jn * 8 + (lane & 3) * 2;
            stage[row * STG_S + col]           = acc[im][jn][0];
            stage[row * STG_S + col + 1]       = acc[im][jn][1];
            stage[(row + 8) * STG_S + col]     = acc[im][jn][2];
            stage[(row + 8) * STG_S + col + 1] = acc[im][jn][3];
        }
    __syncthreads();

    if (tid < 192) {
        int row = tid & 63;
        int seg = tid >> 6;
        int m = m0 + row;
        float f[64];
#pragma unroll
        for (int c = 0; c < 64; c++) f[c] = stage[row * STG_S + seg * 64 + c];
        if (seg < 2) {
            const float* gamma = (seg == 0) ? q_gamma : k_gamma;
            const float* beta  = (seg == 0) ? q_beta  : k_beta;
            float s = 0.f;
#pragma unroll
            for (int c = 0; c < 64; c++) s += f[c];
            float mu = s * (1.f / 64.f);
            float v2 = 0.f;
#pragma unroll
            for (int c = 0; c < 64; c++) { float d = f[c] - mu; v2 += d * d; }
            float rstd = rsqrtf(v2 * (1.f / 64.f) + 1e-5f);
#pragma unroll
            for (int c = 0; c < 64; c++) f[c] = (f[c] - mu) * rstd * gamma[c] + beta[c];
        }
        if (seg == 0) {
            size_t dst = (size_t)m * H_DIM;
#pragma unroll
            for (int c4 = 0; c4 < 16; c4++)
                *(float4*)&g_q[dst + c4 * 4] =
                    make_float4(f[c4 * 4], f[c4 * 4 + 1], f[c4 * 4 + 2], f[c4 * 4 + 3]);
        } else if (seg == 1) {
            uint32_t hp[32], lp[32];
#pragma unroll
            for (int c2 = 0; c2 < 32; c2++) {
                __nv_bfloat16 h0 = __float2bfloat16(f[2 * c2]);
                __nv_bfloat16 h1 = __float2bfloat16(f[2 * c2 + 1]);
                __nv_bfloat16 l0 = __float2bfloat16(f[2 * c2] - __bfloat162float(h0));
                __nv_bfloat16 l1 = __float2bfloat16(f[2 * c2 + 1] - __bfloat162float(h1));
                hp[c2] = packbf(h0, h1);
                lp[c2] = packbf(l0, l1);
            }
            uint4* dh = (uint4*)(g_k_hi + (size_t)m * H_DIM);
            uint4* dl = (uint4*)(g_k_lo + (size_t)m * H_DIM);
#pragma unroll
            for (int c = 0; c < 8; c++) {
                dh[c] = *(uint4*)&hp[c * 4];
                dl[c] = *(uint4*)&lp[c * 4];
            }
        } else {
            int bb = m / T_LEN;
            int t  = m - bb * T_LEN;
            __nv_bfloat16* dh = g_vT_hi + ((size_t)bb * H_DIM) * TPAD + t;
            __nv_bfloat16* dl = g_vT_lo + ((size_t)bb * H_DIM) * TPAD + t;
#pragma unroll
            for (int h = 0; h < 64; h++) {
                __nv_bfloat16 hi = __float2bfloat16(f[h]);
                __nv_bfloat16 lo = __float2bfloat16(f[h] - __bfloat162float(hi));
                dh[(size_t)h * TPAD] = hi;
                dl[(size_t)h * TPAD] = lo;
            }
        }
    }
}

// ---------------------------------------------------------------------------
// Kernel 2 (v10): mma.sync flash attention — 128 threads, QT=64, 3 CTAs/SM.
// Q staged inside KB(1) (aliased; consumed before tile 1 arrives);
// grid coords/masks computed inline (no tables). smem = 73.2 KB.
// ---------------------------------------------------------------------------
#define KT 64
#define NKT 10
#define QT 64
#define KB(i)  ((i) * 36864)
#define KB_KLO 9216
#define KB_VHI 18432
#define KB_VLO 27648
#define AQ_HI  36864            // staged inside KB(1), consumed before tile 1
#define AQ_LO  (AQ_HI + 9216)
#define AP_OFF 73728            // params: al,ix,iy,gx,gy (5*64 floats)
#define A_TOTAL (AP_OFF + 5 * QT * 4)

__device__ __forceinline__ void attn_cp_tile(uint32_t sb, int tid, int krow0, int vbase, int k0,
                                             uint32_t buf)
{
#pragma unroll
    for (int it = 0; it < 4; it++) {
        int i = tid + it * 128;
        int r = i >> 3, seg = i & 7;
        uint32_t soff = sb + buf + (uint32_t)(r * AS + seg * 16);
        size_t g = ((size_t)(krow0 + r)) * H_DIM + seg * 8;
        cp16(soff,          g_k_hi + g);
        cp16(soff + KB_KLO, g_k_lo + g);
    }
#pragma unroll
    for (int it = 0; it < 4; it++) {
        int i = tid + it * 128;
        int h = i >> 3, seg = i & 7;
        uint32_t soff = sb + buf + KB_VHI + (uint32_t)(h * AS + seg * 16);
        size_t g = ((size_t)(vbase + h)) * TPAD + k0 + seg * 8;
        cp16(soff,                     g_vT_hi + g);
        cp16(soff + (KB_VLO - KB_VHI), g_vT_lo + g);
    }
}

__global__ __launch_bounds__(128) void attn_mma_kernel(
    const float* __restrict__ w_sigma, const float* __restrict__ b_sigma,
    const float* __restrict__ w_alpha, const float* __restrict__ b_alpha,
    float* __restrict__ out)
{
    extern __shared__ char smc[];
    const uint32_t sb = smem_u32(smc);
    float* al_s = (float*)(smc + AP_OFF);
    float* ix_s = al_s + QT;
    float* iy_s = ix_s + QT;
    float* gx_s = iy_s + QT;
    float* gy_s = gx_s + QT;

    const int tid  = threadIdx.x;
    const int lane = tid & 31;
    const int wid  = tid >> 5;     // 0..3
    const int b    = blockIdx.y;
    const int q0   = blockIdx.x * QT;
    const size_t base = (size_t)b * T_LEN * H_DIM;
    const int krow0 = b * T_LEN;
    const int vbase = b * H_DIM;

    // stream tile 0 now; tile 1 AFTER Q is consumed (Q aliases KB(1))
    attn_cp_tile(sb, tid, krow0 + 0, vbase, 0, KB(0));
    CP_COMMIT();

    // ---- stage Q (fold 0.125), split bf16 hi/lo, into KB(1) region ----
#pragma unroll
    for (int it = 0; it < 8; it++) {
        int i = tid + it * 128;
        int r = i >> 4, c4 = i & 15;
        int qi = q0 + r;
        float4 v = make_float4(0.f, 0.f, 0.f, 0.f);
        if (qi < T_LEN) v = *(const float4*)&g_q[base + (size_t)qi * H_DIM + c4 * 4];
        v.x *= 0.125f; v.y *= 0.125f; v.z *= 0.125f; v.w *= 0.125f;
        __nv_bfloat16 h0 = __float2bfloat16(v.x), h1 = __float2bfloat16(v.y);
        __nv_bfloat16 h2 = __float2bfloat16(v.z), h3 = __float2bfloat16(v.w);
        __nv_bfloat16 l0 = __float2bfloat16(v.x - __bfloat162float(h0));
        __nv_bfloat16 l1 = __float2bfloat16(v.y - __bfloat162float(h1));
        __nv_bfloat16 l2 = __float2bfloat16(v.z - __bfloat162float(h2));
        __nv_bfloat16 l3 = __float2bfloat16(v.w - __bfloat162float(h3));
        uint32_t off = (uint32_t)(r * AS + c4 * 8);
        *(uint2*)(smc + AQ_HI + off) = make_uint2(packbf(h0, h1), packbf(h2, h3));
        *(uint2*)(smc + AQ_LO + off) = make_uint2(packbf(l0, l1), packbf(l2, l3));
    }

    // ---- per-q-row aug params ----
    if (tid < QT) {
        int r = tid;
        int qi = q0 + r;
        if (qi >= 1 && qi < T_LEN) {
            const float* qrow = &g_q[base + (size_t)qi * H_DIM];
            float a = 0.f, s0 = 0.f, s1 = 0.f;
#pragma unroll 8
            for (int c = 0; c < 64; c++) {
                float qv = qrow[c];
                a  += qv * w_alpha[c];
                s0 += qv * w_sigma[c * 2 + 0];
                s1 += qv * w_sigma[c * 2 + 1];
            }
            a += b_alpha[0]; s0 += b_sigma[0]; s1 += b_sigma[1];
            float alpha = fmaxf(a, 0.f) + log1pf(expf(-fabsf(a)));
            float sx = 1.f / (1.f + expf(-s0));
            float sy = 1.f / (1.f + expf(-s1));
            al_s[r] = alpha * 0.125f;
            ix_s[r] = 0.5f / (sx * sx);
            iy_s[r] = 0.5f / (sy * sy);
            int gq = qi - 1;
            gx_s[r] = (float)(gq % GW);
            gy_s[r] = (float)(gq / GW);
        } else {
            al_s[r] = 0.f; ix_s[r] = 0.f; iy_s[r] = 0.f;
            gx_s[r] = 0.f; gy_s[r] = 0.f;
        }
    }
    __syncthreads();   // Q staged + params visible

    // ---- Q fragments resident in registers (warp w: rows 16w..16w+15) ----
    uint32_t qh[4][4], ql[4][4];
    {
        uint32_t aOff = (uint32_t)((wid * 16 + (lane & 15)) * AS + (lane >> 4) * 16);
#pragma unroll
        for (int c = 0; c < 4; c++) {
            ldsm_x4(qh[c], sb + AQ_HI + aOff + c * 32);
            ldsm_x4(ql[c], sb + AQ_LO + aOff + c * 32);
        }
    }
    __syncthreads();   // all warps done reading Q region
    // now safe to stream tile 1 into KB(1)
    attn_cp_tile(sb, tid, krow0 + KT, vbase, KT, KB(1));
    CP_COMMIT();

    const int r1  = lane >> 2;
    const int lr1 = wid * 16 + r1;
    const float al1 = al_s[lr1],     ix1 = ix_s[lr1],     iy1 = iy_s[lr1];
    const float gx1 = gx_s[lr1],     gy1 = gy_s[lr1];
    const float al2 = al_s[lr1 + 8], ix2 = ix_s[lr1 + 8], iy2 = iy_s[lr1 + 8];
    const float gx2 = gx_s[lr1 + 8], gy2 = gy_s[lr1 + 8];

    float m1 = -1e30f, m2 = -1e30f, l1 = 0.f, l2 = 0.f;
    float oacc[8][4];
#pragma unroll
    for (int n = 0; n < 8; n++)
#pragma unroll
        for (int c = 0; c < 4; c++) oacc[n][c] = 0.f;

    for (int kt = 0; kt < NKT; kt++) {
        const int k0 = kt * KT;
        const int cur = kt & 1;
        if (kt < NKT - 1) CP_WAIT1(); else CP_WAIT0();
        __syncthreads();

        const uint32_t kHi = sb + KB(cur);
        const uint32_t vHi = sb + KB(cur) + KB_VHI;

        // ---- sim = Q @ K^T ----
        float sc[8][4];
#pragma unroll
        for (int n = 0; n < 8; n++)
#pragma unroll
            for (int c = 0; c < 4; c++) sc[n][c] = 0.f;

#pragma unroll
        for (int c = 0; c < 4; c++) {
#pragma unroll
            for (int g = 0; g < 4; g++) {
                uint32_t bOff = (uint32_t)((g * 16 + ((lane >> 4) << 3) + (lane & 7)) * AS
                                           + ((lane >> 3) & 1) * 16 + c * 32);
                uint32_t th[4], tl[4];
                ldsm_x4(th, kHi + bOff);
                ldsm_x4(tl, kHi + KB_KLO + bOff);
                mma_bf16(sc[2 * g],     qh[c], th);
                mma_bf16(sc[2 * g],     qh[c], tl);
                mma_bf16(sc[2 * g],     ql[c], th);
                mma_bf16(sc[2 * g + 1], qh[c], th + 2);
                mma_bf16(sc[2 * g + 1], qh[c], tl + 2);
                mma_bf16(sc[2 * g + 1], ql[c], th + 2);
            }
        }

        // ---- Gaussian aug + mask (coords/masks inline) ----
#pragma unroll
        for (int n = 0; n < 8; n++) {
            int kia = k0 + n * 8 + (lane & 3) * 2;
            int kib = kia + 1;
            float adda1 = 0.f, adda2 = 0.f, kma = 0.f;
            if (kia < T_LEN) {
                if (kia >= 1) {
                    int g = kia - 1;
                    float kx = (float)(g % GW), ky = (float)(g / GW);
                    float dx1 = gx1 - kx, dy1 = gy1 - ky;
                    float dx2 = gx2 - kx, dy2 = gy2 - ky;
                    adda1 = al1 * __expf(-dx1 * dx1 * ix1 - dy1 * dy1 * iy1);
                    adda2 = al2 * __expf(-dx2 * dx2 * ix2 - dy2 * dy2 * iy2);
                }
            } else kma = -1e30f;
            float addb1 = 0.f, addb2 = 0.f, kmb = 0.f;
            if (kib < T_LEN) {
                if (kib >= 1) {
                    int g = kib - 1;
                    float kx = (float)(g % GW), ky = (float)(g / GW);
                    float dx1 = gx1 - kx, dy1 = gy1 - ky;
                    float dx2 = gx2 - kx, dy2 = gy2 - ky;
                    addb1 = al1 * __expf(-dx1 * dx1 * ix1 - dy1 * dy1 * iy1);
                    addb2 = al2 * __expf(-dx2 * dx2 * ix2 - dy2 * dy2 * iy2);
                }
            } else kmb = -1e30f;
            sc[n][0] += adda1 + kma;
            sc[n][1] += addb1 + kmb;
            sc[n][2] += adda2 + kma;
            sc[n][3] += addb2 + kmb;
        }

        // ---- online softmax ----
        float mx1 = -1e30f, mx2 = -1e30f;
#pragma unroll
        for (int n = 0; n < 8; n++) {
            mx1 = fmaxf(mx1, fmaxf(sc[n][0], sc[n][1]));
            mx2 = fmaxf(mx2, fmaxf(sc[n][2], sc[n][3]));
        }
        mx1 = fmaxf(mx1, __shfl_xor_sync(0xffffffffu, mx1, 1));
        mx1 = fmaxf(mx1, __shfl_xor_sync(0xffffffffu, mx1, 2));
        mx2 = fmaxf(mx2, __shfl_xor_sync(0xffffffffu, mx2, 1));
        mx2 = fmaxf(mx2, __shfl_xor_sync(0xffffffffu, mx2, 2));

        float mnew1 = fmaxf(m1, mx1), mnew2 = fmaxf(m2, mx2);
        float scf1 = __expf(m1 - mnew1), scf2 = __expf(m2 - mnew2);
        m1 = mnew1; m2 = mnew2;

        float sum1 = 0.f, sum2 = 0.f;
#pragma unroll
        for (int n = 0; n < 8; n++) {
            float p0 = __expf(sc[n][0] - m1);
            float p1 = __expf(sc[n][1] - m1);
            float p2 = __expf(sc[n][2] - m2);
            float p3 = __expf(sc[n][3] - m2);
            sc[n][0] = p0; sc[n][1] = p1; sc[n][2] = p2; sc[n][3] = p3;
            sum1 += p0 + p1; sum2 += p2 + p3;
        }
        sum1 += __shfl_xor_sync(0xffffffffu, sum1, 1);
        sum1 += __shfl_xor_sync(0xffffffffu, sum1, 2);
        sum2 += __shfl_xor_sync(0xffffffffu, sum2, 1);
        sum2 += __shfl_xor_sync(0xffffffffu, sum2, 2);
        l1 = l1 * scf1 + sum1;
        l2 = l2 * scf2 + sum2;
#pragma unroll
        for (int n = 0; n < 8; n++) {
            oacc[n][0] *= scf1; oacc[n][1] *= scf1;
            oacc[n][2] *= scf2; oacc[n][3] *= scf2;
        }

        // ---- PV ----
#pragma unroll
        for (int c = 0; c < 4; c++) {
            uint32_t ahi[4], alo[4];
#pragma unroll
            for (int t = 0; t < 2; t++) {
                float p0 = sc[2 * c + t][0], p1 = sc[2 * c + t][1];
                float p2 = sc[2 * c + t][2], p3 = sc[2 * c + t][3];
                uint32_t h01 = pk_bf2(p0, p1);
                uint32_t h23 = pk_bf2(p2, p3);
                float r0 = p0 - __uint_as_float(h01 << 16);
                float r1b = p1 - __uint_as_float(h01 & 0xffff0000u);
                float r2 = p2 - __uint_as_float(h23 << 16);
                float r3 = p3 - __uint_as_float(h23 & 0xffff0000u);
                ahi[2 * t]     = h01;
                ahi[2 * t + 1] = h23;
                alo[2 * t]     = pk_bf2(r0, r1b);
                alo[2 * t + 1] = pk_bf2(r2, r3);
            }
            uint32_t af_hi[4] = {ahi[0], ahi[1], ahi[2], ahi[3]};
            uint32_t af_lo[4] = {alo[0], alo[1], alo[2], alo[3]};
#pragma unroll
            for (int g = 0; g < 4; g++) {
                uint32_t bOff = (uint32_t)((g * 16 + ((lane >> 4) << 3) + (lane & 7)) * AS
                                           + ((lane >> 3) & 1) * 16 + c * 32);
                uint32_t th[4], tl[4];
                ldsm_x4(th, vHi + bOff);
                ldsm_x4(tl, vHi + (KB_VLO - KB_VHI) + bOff);
                mma_bf16(oacc[2 * g],     af_hi, th);
                mma_bf16(oacc[2 * g],     af_hi, tl);
                mma_bf16(oacc[2 * g],     af_lo, th);
                mma_bf16(oacc[2 * g + 1], af_hi, th + 2);
                mma_bf16(oacc[2 * g + 1], af_hi, tl + 2);
                mma_bf16(oacc[2 * g + 1], af_lo, th + 2);
            }
        }

        __syncthreads();   // done reading buffer cur
        if (kt < NKT - 2) {
            const int k0n = (kt + 2) * KT;
            attn_cp_tile(sb, tid, krow0 + k0n, vbase, k0n, KB(cur));
            CP_COMMIT();
        }
    }

    // ---- final normalize + write ----
    float inv1 = 1.f / l1, inv2 = 1.f / l2;
    int qi1 = q0 + wid * 16 + r1;
    int qi2 = qi1 + 8;
#pragma unroll
    for (int n = 0; n < 8; n++) {
        int h = n * 8 + (lane & 3) * 2;
        if (qi1 < T_LEN) {
            float2 o = make_float2(oacc[n][0] * inv1, oacc[n][1] * inv1);
            *(float2*)&out[base + (size_t)qi1 * H_DIM + h] = o;
        }
        if (qi2 < T_LEN) {
            float2 o = make_float2(oacc[n][2] * inv2, oacc[n][3] * inv2);
            *(float2*)&out[base + (size_t)qi2 * H_DIM + h] = o;
        }
    }
}

// ---------------------------------------------------------------------------
extern "C" void kernel_launch(void* const* d_in, const int* in_sizes, int n_in,
                              void* d_out, int out_size)
{
    const float* x       = (const float*)d_in[0];
    const float* w_q     = (const float*)d_in[1];
    const float* w_k     = (const float*)d_in[2];
    const float* w_v     = (const float*)d_in[3];
    const float* q_gamma = (const float*)d_in[4];
    const float* q_beta  = (const float*)d_in[5];
    const float* k_gamma = (const float*)d_in[6];
    const float* k_beta  = (const float*)d_in[7];
    const float* w_sigma = (const float*)d_in[8];
    const float* b_sigma = (const float*)d_in[9];
    const float* w_alpha = (const float*)d_in[10];
    const float* b_alpha = (const float*)d_in[11];
    float* out = (float*)d_out;

    prep_w_kernel<<<(192 * E_DIM + 255) / 256, 256>>>(w_q, w_k, w_v);
    pad_kernel<<<(B_SZ * H_DIM * (TPAD - T_LEN) + 255) / 256, 256>>>();

    cudaFuncSetAttribute(qkv_mma_kernel, cudaFuncAttributeMaxDynamicSharedMemorySize, SM_TOTAL);
    qkv_mma_kernel<<<M_ROWS / 64, 256, SM_TOTAL>>>(x, q_gamma, q_beta, k_gamma, k_beta);

    cudaFuncSetAttribute(attn_mma_kernel, cudaFuncAttributeMaxDynamicSharedMemorySize, A_TOTAL);
    dim3 grid2((T_LEN + QT - 1) / QT, B_SZ);
    attn_mma_kernel<<<grid2, 128, A_TOTAL>>>(w_sigma, b_sigma, w_alpha, b_alpha, out);
}

// round 16
// speedup vs baseline: 1.0713x; 1.0713x over previous
#include <cuda_runtime.h>
#include <cuda_bf16.h>
#include <math.h>
#include <stdint.h>

#define M_ROWS 36928   // B*T = 64*577
#define E_DIM  768
#define H_DIM  64
#define T_LEN  577
#define B_SZ   64
#define GW     24
#define TPAD   640     // padded T for transposed V

// scratch (static device arrays; no allocation)
__device__ float g_q[M_ROWS * H_DIM];
__device__ __nv_bfloat16 g_k_hi[(M_ROWS + 64) * H_DIM];
__device__ __nv_bfloat16 g_k_lo[(M_ROWS + 64) * H_DIM];
__device__ __nv_bfloat16 g_vT_hi[B_SZ * H_DIM * TPAD];
__device__ __nv_bfloat16 g_vT_lo[B_SZ * H_DIM * TPAD];
__device__ __nv_bfloat16 g_wcat_hi[192 * E_DIM];
__device__ __nv_bfloat16 g_wcat_lo[192 * E_DIM];

__device__ __forceinline__ uint32_t smem_u32(const void* p) {
    uint32_t a;
    asm("{ .reg .u64 t; cvta.to.shared.u64 t, %1; cvt.u32.u64 %0, t; }" : "=r"(a) : "l"(p));
    return a;
}
__device__ __forceinline__ void ldsm_x4(uint32_t* r, uint32_t addr) {
    asm volatile("ldmatrix.sync.aligned.m8n8.x4.shared.b16 {%0,%1,%2,%3}, [%4];"
                 : "=r"(r[0]), "=r"(r[1]), "=r"(r[2]), "=r"(r[3]) : "r"(addr));
}
__device__ __forceinline__ void mma_bf16(float* d, const uint32_t* a, const uint32_t* b) {
    asm volatile(
        "mma.sync.aligned.m16n8k16.row.col.f32.bf16.bf16.f32 "
        "{%0,%1,%2,%3}, {%4,%5,%6,%7}, {%8,%9}, {%0,%1,%2,%3};"
        : "+f"(d[0]), "+f"(d[1]), "+f"(d[2]), "+f"(d[3])
        : "r"(a[0]), "r"(a[1]), "r"(a[2]), "r"(a[3]), "r"(b[0]), "r"(b[1]));
}
__device__ __forceinline__ uint32_t packbf(__nv_bfloat16 a, __nv_bfloat16 b) {
    uint16_t ua = *(uint16_t*)&a, ub = *(uint16_t*)&b;
    return (uint32_t)ua | ((uint32_t)ub << 16);
}
__device__ __forceinline__ uint32_t pk_bf2(float lo, float hi) {
    uint32_t r; asm("cvt.rn.bf16x2.f32 %0, %1, %2;" : "=r"(r) : "f"(hi), "f"(lo)); return r;
}
__device__ __forceinline__ void cp16(uint32_t saddr, const void* gaddr) {
    asm volatile("cp.async.ca.shared.global [%0], [%1], 16;" :: "r"(saddr), "l"(gaddr) : "memory");
}
#define CP_COMMIT() asm volatile("cp.async.commit_group;" ::: "memory")
#define CP_WAIT1()  asm volatile("cp.async.wait_group 1;" ::: "memory")
#define CP_WAIT0()  asm volatile("cp.async.wait_group 0;" ::: "memory")

// ---------------------------------------------------------------------------
// Kernel 0a: weight prep
// ---------------------------------------------------------------------------
__global__ void prep_w_kernel(const float* __restrict__ w_q, const float* __restrict__ w_k,
                              const float* __restrict__ w_v)
{
    int idx = blockIdx.x * blockDim.x + threadIdx.x;
    if (idx >= 192 * E_DIM) return;
    int n = idx / E_DIM, k = idx % E_DIM;
    const float* w = (n < 64) ? w_q : (n < 128) ? w_k : w_v;
    float v = w[k * H_DIM + (n & 63)];
    __nv_bfloat16 hi = __float2bfloat16(v);
    __nv_bfloat16 lo = __float2bfloat16(v - __bfloat162float(hi));
    g_wcat_hi[idx] = hi;
    g_wcat_lo[idx] = lo;
}

// ---------------------------------------------------------------------------
// Kernel 0b: zero padding regions
// ---------------------------------------------------------------------------
__global__ void pad_kernel()
{
    int idx = blockIdx.x * blockDim.x + threadIdx.x;
    const __nv_bfloat16 z = __float2bfloat16(0.f);
    if (idx < 64 * H_DIM) {
        g_k_hi[(size_t)M_ROWS * H_DIM + idx] = z;
        g_k_lo[(size_t)M_ROWS * H_DIM + idx] = z;
    }
    const int NPAD = TPAD - T_LEN;
    const int NV = B_SZ * H_DIM * NPAD;
    if (idx < NV) {
        int b = idx / (H_DIM * NPAD);
        int rem = idx % (H_DIM * NPAD);
        int h = rem / NPAD;
        int j = rem % NPAD;
        size_t pos = ((size_t)(b * H_DIM + h)) * TPAD + T_LEN + j;
        g_vT_hi[pos] = z;
        g_vT_lo[pos] = z;
    }
}

// ---------------------------------------------------------------------------
// Kernel 1 (v2): split-bf16 mma.sync QKV GEMM + LayerNorm.
// GK=32 chunks -> 81.9 KB smem -> 2 CTAs/SM for latency hiding.
// ---------------------------------------------------------------------------
#define GK 32
#define NCHUNK (E_DIM / GK)             // 24
#define QAS 80                          // qkv tile row stride (bytes)
#define QA_LO_OFF (64 * QAS)            // 5120
#define ABUF(i) ((i) * 2 * QA_LO_OFF)   // 10240 per buffer
#define QB_LO_OFF (192 * QAS)           // 15360
#define BBUF(i) (20480 + (i) * 2 * QB_LO_OFF)  // 30720 per buffer
#define SM_TOTAL (20480 + 2 * 30720)    // 81920
#define STG_S 201

__device__ __forceinline__ void qkv_store_A(char* smc, int tid, const float4* av, uint32_t abuf)
{
#pragma unroll
    for (int it = 0; it < 2; it++) {
        int i = tid + it * 256;              // 0..511
        int r = i >> 3, col = (i & 7) * 4;
        float4 v = av[it];
        __nv_bfloat16 h0 = __float2bfloat16(v.x), h1 = __float2bfloat16(v.y);
        __nv_bfloat16 h2 = __float2bfloat16(v.z), h3 = __float2bfloat16(v.w);
        __nv_bfloat16 l0 = __float2bfloat16(v.x - __bfloat162float(h0));
        __nv_bfloat16 l1 = __float2bfloat16(v.y - __bfloat162float(h1));
        __nv_bfloat16 l2 = __float2bfloat16(v.z - __bfloat162float(h2));
        __nv_bfloat16 l3 = __float2bfloat16(v.w - __bfloat162float(h3));
        uint32_t off = abuf + (uint32_t)(r * QAS + col * 2);
        *(uint2*)(smc + off)             = make_uint2(packbf(h0, h1), packbf(h2, h3));
        *(uint2*)(smc + off + QA_LO_OFF) = make_uint2(packbf(l0, l1), packbf(l2, l3));
    }
}
__device__ __forceinline__ void qkv_cp_B(uint32_t sb, int tid, int k0, uint32_t bbuf)
{
#pragma unroll
    for (int it = 0; it < 3; it++) {
        int i = tid + it * 256;              // 0..767 = 192 rows x 4 segs
        int r = i >> 2, seg = i & 3;
        uint32_t soff = sb + bbuf + (uint32_t)(r * QAS + seg * 16);
        size_t goff = (size_t)r * E_DIM + k0 + seg * 8;
        cp16(soff,             g_wcat_hi + goff);
        cp16(soff + QB_LO_OFF, g_wcat_lo + goff);
    }
}

__global__ __launch_bounds__(256, 2) void qkv_mma_kernel(
    const float* __restrict__ x,
    const float* __restrict__ q_gamma, const float* __restrict__ q_beta,
    const float* __restrict__ k_gamma, const float* __restrict__ k_beta)
{
    extern __shared__ char smc[];
    const uint32_t sb = smem_u32(smc);
    const int tid  = threadIdx.x;
    const int wid  = tid >> 5;
    const int lane = tid & 31;
    const int wm   = wid >> 2;
    const int wn   = wid & 3;
    const int m0   = blockIdx.x * 64;

    const uint32_t aOff = (uint32_t)((wm * 32 + (lane & 15)) * QAS + (lane >> 4) * 16);
    const uint32_t bOff = (uint32_t)((wn * 48 + ((lane >> 4) << 3) + (lane & 7)) * QAS
                                     + ((lane >> 3) & 1) * 16);

    float acc[2][6][4];
#pragma unroll
    for (int i = 0; i < 2; i++)
#pragma unroll
        for (int j = 0; j < 6; j++)
#pragma unroll
            for (int c = 0; c < 4; c++) acc[i][j][c] = 0.f;

    float4 av[2];
    qkv_cp_B(sb, tid, 0, BBUF(0));
    CP_COMMIT();
#pragma unroll
    for (int it = 0; it < 2; it++) {
        int i = tid + it * 256;
        int r = i >> 3, col = (i & 7) * 4;
        av[it] = *(const float4*)&x[(size_t)(m0 + r) * E_DIM + 0 + col];
    }
    qkv_store_A(smc, tid, av, ABUF(0));
    qkv_cp_B(sb, tid, GK, BBUF(1));
    CP_COMMIT();
#pragma unroll
    for (int it = 0; it < 2; it++) {
        int i = tid + it * 256;
        int r = i >> 3, col = (i & 7) * 4;
        av[it] = *(const float4*)&x[(size_t)(m0 + r) * E_DIM + GK + col];
    }

    for (int ch = 0; ch < NCHUNK; ch++) {
        const int cur = ch & 1;
        if (ch < NCHUNK - 1) CP_WAIT1(); else CP_WAIT0();
        __syncthreads();

        const uint32_t aHi = sb + ABUF(cur) + aOff;
        const uint32_t bHi = sb + BBUF(cur) + bOff;
#pragma unroll
        for (int ks = 0; ks < 2; ks++) {
            const uint32_t kb = (uint32_t)(ks * 32);
            uint32_t ahi[2][4], alo[2][4];
#pragma unroll
            for (int im = 0; im < 2; im++) {
                ldsm_x4(ahi[im], aHi + im * 16 * QAS + kb);
                ldsm_x4(alo[im], aHi + QA_LO_OFF + im * 16 * QAS + kb);
            }
            uint32_t bhi[6][2], blo[6][2];
#pragma unroll
            for (int j = 0; j < 3; j++) {
                uint32_t t[4];
                ldsm_x4(t, bHi + j * 16 * QAS + kb);
                bhi[2 * j][0] = t[0]; bhi[2 * j][1] = t[1];
                bhi[2 * j + 1][0] = t[2]; bhi[2 * j + 1][1] = t[3];
                ldsm_x4(t, bHi + QB_LO_OFF + j * 16 * QAS + kb);
                blo[2 * j][0] = t[0]; blo[2 * j][1] = t[1];
                blo[2 * j + 1][0] = t[2]; blo[2 * j + 1][1] = t[3];
            }
#pragma unroll
            for (int im = 0; im < 2; im++)
#pragma unroll
                for (int jn = 0; jn < 6; jn++) {
                    mma_bf16(acc[im][jn], ahi[im], bhi[jn]);
                    mma_bf16(acc[im][jn], ahi[im], blo[jn]);
                    mma_bf16(acc[im][jn], alo[im], bhi[jn]);
                }
        }

        if (ch < NCHUNK - 1)
            qkv_store_A(smc, tid, av, ABUF((ch + 1) & 1));
        __syncthreads();

        if (ch < NCHUNK - 2) {
            const int k0n = (ch + 2) * GK;
            qkv_cp_B(sb, tid, k0n, BBUF(cur));
            CP_COMMIT();
#pragma unroll
            for (int it = 0; it < 2; it++) {
                int i = tid + it * 256;
                int r = i >> 3, col = (i & 7) * 4;
                av[it] = *(const float4*)&x[(size_t)(m0 + r) * E_DIM + k0n + col];
            }
        }
    }
    __syncthreads();

    float* stage = (float*)smc;
#pragma unroll
    for (int im = 0; im < 2; im++)
#pragma unroll
        for (int jn = 0; jn < 6; jn++) {
            int row = wm * 32 + im * 16 + (lane >> 2);
            int col = wn * 48 + jn * 8 + (lane & 3) * 2;
            stage[row * STG_S + col]           = acc[im][jn][0];
            stage[row * STG_S + col + 1]       = acc[im][jn][1];
            stage[(row + 8) * STG_S + col]     = acc[im][jn][2];
            stage[(row + 8) * STG_S + col + 1] = acc[im][jn][3];
        }
    __syncthreads();

    if (tid < 192) {
        int row = tid & 63;
        int seg = tid >> 6;
        int m = m0 + row;
        float f[64];
#pragma unroll
        for (int c = 0; c < 64; c++) f[c] = stage[row * STG_S + seg * 64 + c];
        if (seg < 2) {
            const float* gamma = (seg == 0) ? q_gamma : k_gamma;
            const float* beta  = (seg == 0) ? q_beta  : k_beta;
            float s = 0.f;
#pragma unroll
            for (int c = 0; c < 64; c++) s += f[c];
            float mu = s * (1.f / 64.f);
            float v2 = 0.f;
#pragma unroll
            for (int c = 0; c < 64; c++) { float d = f[c] - mu; v2 += d * d; }
            float rstd = rsqrtf(v2 * (1.f / 64.f) + 1e-5f);
#pragma unroll
            for (int c = 0; c < 64; c++) f[c] = (f[c] - mu) * rstd * gamma[c] + beta[c];
        }
        if (seg == 0) {
            size_t dst = (size_t)m * H_DIM;
#pragma unroll
            for (int c4 = 0; c4 < 16; c4++)
                *(float4*)&g_q[dst + c4 * 4] =
                    make_float4(f[c4 * 4], f[c4 * 4 + 1], f[c4 * 4 + 2], f[c4 * 4 + 3]);
        } else if (seg == 1) {
            uint32_t hp[32], lp[32];
#pragma unroll
            for (int c2 = 0; c2 < 32; c2++) {
                __nv_bfloat16 h0 = __float2bfloat16(f[2 * c2]);
                __nv_bfloat16 h1 = __float2bfloat16(f[2 * c2 + 1]);
                __nv_bfloat16 l0 = __float2bfloat16(f[2 * c2] - __bfloat162float(h0));
                __nv_bfloat16 l1 = __float2bfloat16(f[2 * c2 + 1] - __bfloat162float(h1));
                hp[c2] = packbf(h0, h1);
                lp[c2] = packbf(l0, l1);
            }
            uint4* dh = (uint4*)(g_k_hi + (size_t)m * H_DIM);
            uint4* dl = (uint4*)(g_k_lo + (size_t)m * H_DIM);
#pragma unroll
            for (int c = 0; c < 8; c++) {
                dh[c] = *(uint4*)&hp[c * 4];
                dl[c] = *(uint4*)&lp[c * 4];
            }
        } else {
            int bb = m / T_LEN;
            int t  = m - bb * T_LEN;
            __nv_bfloat16* dh = g_vT_hi + ((size_t)bb * H_DIM) * TPAD + t;
            __nv_bfloat16* dl = g_vT_lo + ((size_t)bb * H_DIM) * TPAD + t;
#pragma unroll
            for (int h = 0; h < 64; h++) {
                __nv_bfloat16 hi = __float2bfloat16(f[h]);
                __nv_bfloat16 lo = __float2bfloat16(f[h] - __bfloat162float(hi));
                dh[(size_t)h * TPAD] = hi;
                dl[(size_t)h * TPAD] = lo;
            }
        }
    }
}

// ---------------------------------------------------------------------------
// Kernel 2 (v9 = R14 exact, measured 96.96us): mma.sync flash attention —
// 128 threads (4 warps), QT=64, 2 CTAs/SM, smem grid tables.
// ---------------------------------------------------------------------------
#define AS 144
#define KT 64
#define NKT 10
#define QT 64
#define AQ_HI 0
#define AQ_LO 9216
#define KB(i)  (18432 + (i) * 36864)
#define KB_KLO 9216
#define KB_VHI 18432
#define KB_VLO 27648
#define AP_OFF 92160
#define A_TOTAL (AP_OFF + (5 * QT + 3 * TPAD) * 4)

__device__ __forceinline__ void attn_cp_tile(uint32_t sb, int tid, int krow0, int vbase, int k0,
                                             uint32_t buf)
{
#pragma unroll
    for (int it = 0; it < 4; it++) {
        int i = tid + it * 128;
        int r = i >> 3, seg = i & 7;
        uint32_t soff = sb + buf + (uint32_t)(r * AS + seg * 16);
        size_t g = ((size_t)(krow0 + r)) * H_DIM + seg * 8;
        cp16(soff,          g_k_hi + g);
        cp16(soff + KB_KLO, g_k_lo + g);
    }
#pragma unroll
    for (int it = 0; it < 4; it++) {
        int i = tid + it * 128;
        int h = i >> 3, seg = i & 7;
        uint32_t soff = sb + buf + KB_VHI + (uint32_t)(h * AS + seg * 16);
        size_t g = ((size_t)(vbase + h)) * TPAD + k0 + seg * 8;
        cp16(soff,                     g_vT_hi + g);
        cp16(soff + (KB_VLO - KB_VHI), g_vT_lo + g);
    }
}

__global__ __launch_bounds__(128) void attn_mma_kernel(
    const float* __restrict__ w_sigma, const float* __restrict__ b_sigma,
    const float* __restrict__ w_alpha, const float* __restrict__ b_alpha,
    float* __restrict__ out)
{
    extern __shared__ char smc[];
    const uint32_t sb = smem_u32(smc);
    float* al_s = (float*)(smc + AP_OFF);
    float* ix_s = al_s + QT;
    float* iy_s = ix_s + QT;
    float* gx_s = iy_s + QT;
    float* gy_s = gx_s + QT;
    float* kxA  = gy_s + QT;       // [TPAD]
    float* kyA  = kxA + TPAD;
    float* kmA  = kyA + TPAD;

    const int tid  = threadIdx.x;
    const int lane = tid & 31;
    const int wid  = tid >> 5;     // 0..3
    const int b    = blockIdx.y;
    const int q0   = blockIdx.x * QT;
    const size_t base = (size_t)b * T_LEN * H_DIM;
    const int krow0 = b * T_LEN;
    const int vbase = b * H_DIM;

    attn_cp_tile(sb, tid, krow0 + 0,  vbase, 0,  KB(0));
    CP_COMMIT();
    attn_cp_tile(sb, tid, krow0 + KT, vbase, KT, KB(1));
    CP_COMMIT();

#pragma unroll
    for (int it = 0; it < 8; it++) {
        int i = tid + it * 128;
        int r = i >> 4, c4 = i & 15;
        int qi = q0 + r;
        float4 v = make_float4(0.f, 0.f, 0.f, 0.f);
        if (qi < T_LEN) v = *(const float4*)&g_q[base + (size_t)qi * H_DIM + c4 * 4];
        v.x *= 0.125f; v.y *= 0.125f; v.z *= 0.125f; v.w *= 0.125f;
        __nv_bfloat16 h0 = __float2bfloat16(v.x), h1 = __float2bfloat16(v.y);
        __nv_bfloat16 h2 = __float2bfloat16(v.z), h3 = __float2bfloat16(v.w);
        __nv_bfloat16 l0 = __float2bfloat16(v.x - __bfloat162float(h0));
        __nv_bfloat16 l1 = __float2bfloat16(v.y - __bfloat162float(h1));
        __nv_bfloat16 l2 = __float2bfloat16(v.z - __bfloat162float(h2));
        __nv_bfloat16 l3 = __float2bfloat16(v.w - __bfloat162float(h3));
        uint32_t off = (uint32_t)(r * AS + c4 * 8);
        *(uint2*)(smc + AQ_HI + off) = make_uint2(packbf(h0, h1), packbf(h2, h3));
        *(uint2*)(smc + AQ_LO + off) = make_uint2(packbf(l0, l1), packbf(l2, l3));
    }

    if (tid < QT) {
        int r = tid;
        int qi = q0 + r;
        if (qi >= 1 && qi < T_LEN) {
            const float* qrow = &g_q[base + (size_t)qi * H_DIM];
            float a = 0.f, s0 = 0.f, s1 = 0.f;
#pragma unroll 8
            for (int c = 0; c < 64; c++) {
                float qv = qrow[c];
                a  += qv * w_alpha[c];
                s0 += qv * w_sigma[c * 2 + 0];
                s1 += qv * w_sigma[c * 2 + 1];
            }
            a += b_alpha[0]; s0 += b_sigma[0]; s1 += b_sigma[1];
            float alpha = fmaxf(a, 0.f) + log1pf(expf(-fabsf(a)));
            float sx = 1.f / (1.f + expf(-s0));
            float sy = 1.f / (1.f + expf(-s1));
            al_s[r] = alpha * 0.125f;
            ix_s[r] = 0.5f / (sx * sx);
            iy_s[r] = 0.5f / (sy * sy);
            int gq = qi - 1;
            gx_s[r] = (float)(gq % GW);
            gy_s[r] = (float)(gq / GW);
        } else {
            al_s[r] = 0.f; ix_s[r] = 0.f; iy_s[r] = 0.f;
            gx_s[r] = 0.f; gy_s[r] = 0.f;
        }
    }
#pragma unroll
    for (int it = 0; it < 5; it++) {
        int ki = tid + it * 128;
        if (ki < TPAD) {
            bool kvalid = ki < T_LEN;
            bool kaug = (ki >= 1) && kvalid;
            int g = kaug ? ki - 1 : 0;
            kxA[ki] = kaug ? (float)(g % GW) : -1e9f;
            kyA[ki] = kaug ? (float)(g / GW) : 0.f;
            kmA[ki] = kvalid ? 0.f : -1e30f;
        }
    }
    __syncthreads();

    uint32_t qh[4][4], ql[4][4];
    {
        uint32_t aOff = (uint32_t)((wid * 16 + (lane & 15)) * AS + (lane >> 4) * 16);
#pragma unroll
        for (int c = 0; c < 4; c++) {
            ldsm_x4(qh[c], sb + AQ_HI + aOff + c * 32);
            ldsm_x4(ql[c], sb + AQ_LO + aOff + c * 32);
        }
    }

    const int r1  = lane >> 2;
    const int lr1 = wid * 16 + r1;
    const float al1 = al_s[lr1],     ix1 = ix_s[lr1],     iy1 = iy_s[lr1];
    const float gx1 = gx_s[lr1],     gy1 = gy_s[lr1];
    const float al2 = al_s[lr1 + 8], ix2 = ix_s[lr1 + 8], iy2 = iy_s[lr1 + 8];
    const float gx2 = gx_s[lr1 + 8], gy2 = gy_s[lr1 + 8];

    float m1 = -1e30f, m2 = -1e30f, l1 = 0.f, l2 = 0.f;
    float oacc[8][4];
#pragma unroll
    for (int n = 0; n < 8; n++)
#pragma unroll
        for (int c = 0; c < 4; c++) oacc[n][c] = 0.f;

    for (int kt = 0; kt < NKT; kt++) {
        const int k0 = kt * KT;
        const int cur = kt & 1;
        if (kt < NKT - 1) CP_WAIT1(); else CP_WAIT0();
        __syncthreads();

        const uint32_t kHi = sb + KB(cur);
        const uint32_t vHi = sb + KB(cur) + KB_VHI;

        float sc[8][4];
#pragma unroll
        for (int n = 0; n < 8; n++)
#pragma unroll
            for (int c = 0; c < 4; c++) sc[n][c] = 0.f;

#pragma unroll
        for (int c = 0; c < 4; c++) {
#pragma unroll
            for (int g = 0; g < 4; g++) {
                uint32_t bOff = (uint32_t)((g * 16 + ((lane >> 4) << 3) + (lane & 7)) * AS
                                           + ((lane >> 3) & 1) * 16 + c * 32);
                uint32_t th[4], tl[4];
                ldsm_x4(th, kHi + bOff);
                ldsm_x4(tl, kHi + KB_KLO + bOff);
                mma_bf16(sc[2 * g],     qh[c], th);
                mma_bf16(sc[2 * g],     qh[c], tl);
                mma_bf16(sc[2 * g],     ql[c], th);
                mma_bf16(sc[2 * g + 1], qh[c], th + 2);
                mma_bf16(sc[2 * g + 1], qh[c], tl + 2);
                mma_bf16(sc[2 * g + 1], ql[c], th + 2);
            }
        }

#pragma unroll
        for (int n = 0; n < 8; n++) {
            int kc0 = k0 + n * 8 + (lane & 3) * 2;
            float kxa = kxA[kc0],     kya = kyA[kc0],     kma = kmA[kc0];
            float kxb = kxA[kc0 + 1], kyb = kyA[kc0 + 1], kmb = kmA[kc0 + 1];
            float dxa1 = gx1 - kxa, dya1 = gy1 - kya;
            float dxb1 = gx1 - kxb, dyb1 = gy1 - kyb;
            float dxa2 = gx2 - kxa, dya2 = gy2 - kya;
            float dxb2 = gx2 - kxb, dyb2 = gy2 - kyb;
            sc[n][0] += al1 * __expf(-dxa1 * dxa1 * ix1 - dya1 * dya1 * iy1) + kma;
            sc[n][1] += al1 * __expf(-dxb1 * dxb1 * ix1 - dyb1 * dyb1 * iy1) + kmb;
            sc[n][2] += al2 * __expf(-dxa2 * dxa2 * ix2 - dya2 * dya2 * iy2) + kma;
            sc[n][3] += al2 * __expf(-dxb2 * dxb2 * ix2 - dyb2 * dyb2 * iy2) + kmb;
        }

        float mx1 = -1e30f, mx2 = -1e30f;
#pragma unroll
        for (int n = 0; n < 8; n++) {
            mx1 = fmaxf(mx1, fmaxf(sc[n][0], sc[n][1]));
            mx2 = fmaxf(mx2, fmaxf(sc[n][2], sc[n][3]));
        }
        mx1 = fmaxf(mx1, __shfl_xor_sync(0xffffffffu, mx1, 1));
        mx1 = fmaxf(mx1, __shfl_xor_sync(0xffffffffu, mx1, 2));
        mx2 = fmaxf(mx2, __shfl_xor_sync(0xffffffffu, mx2, 1));
        mx2 = fmaxf(mx2, __shfl_xor_sync(0xffffffffu, mx2, 2));

        float mnew1 = fmaxf(m1, mx1), mnew2 = fmaxf(m2, mx2);
        float scf1 = __expf(m1 - mnew1), scf2 = __expf(m2 - mnew2);
        m1 = mnew1; m2 = mnew2;

        float sum1 = 0.f, sum2 = 0.f;
#pragma unroll
        for (int n = 0; n < 8; n++) {
            float p0 = __expf(sc[n][0] - m1);
            float p1 = __expf(sc[n][1] - m1);
            float p2 = __expf(sc[n][2] - m2);
            float p3 = __expf(sc[n][3] - m2);
            sc[n][0] = p0; sc[n][1] = p1; sc[n][2] = p2; sc[n][3] = p3;
            sum1 += p0 + p1; sum2 += p2 + p3;
        }
        sum1 += __shfl_xor_sync(0xffffffffu, sum1, 1);
        sum1 += __shfl_xor_sync(0xffffffffu, sum1, 2);
        sum2 += __shfl_xor_sync(0xffffffffu, sum2, 1);
        sum2 += __shfl_xor_sync(0xffffffffu, sum2, 2);
        l1 = l1 * scf1 + sum1;
        l2 = l2 * scf2 + sum2;
#pragma unroll
        for (int n = 0; n < 8; n++) {
            oacc[n][0] *= scf1; oacc[n][1] *= scf1;
            oacc[n][2] *= scf2; oacc[n][3] *= scf2;
        }

#pragma unroll
        for (int c = 0; c < 4; c++) {
            uint32_t ahi[4], alo[4];
#pragma unroll
            for (int t = 0; t < 2; t++) {
                float p0 = sc[2 * c + t][0], p1 = sc[2 * c + t][1];
                float p2 = sc[2 * c + t][2], p3 = sc[2 * c + t][3];
                uint32_t h01 = pk_bf2(p0, p1);
                uint32_t h23 = pk_bf2(p2, p3);
                float r0 = p0 - __uint_as_float(h01 << 16);
                float r1b = p1 - __uint_as_float(h01 & 0xffff0000u);
                float r2 = p2 - __uint_as_float(h23 << 16);
                float r3 = p3 - __uint_as_float(h23 & 0xffff0000u);
                ahi[2 * t]     = h01;
                ahi[2 * t + 1] = h23;
                alo[2 * t]     = pk_bf2(r0, r1b);
                alo[2 * t + 1] = pk_bf2(r2, r3);
            }
            uint32_t af_hi[4] = {ahi[0], ahi[1], ahi[2], ahi[3]};
            uint32_t af_lo[4] = {alo[0], alo[1], alo[2], alo[3]};
#pragma unroll
            for (int g = 0; g < 4; g++) {
                uint32_t bOff = (uint32_t)((g * 16 + ((lane >> 4) << 3) + (lane & 7)) * AS
                                           + ((lane >> 3) & 1) * 16 + c * 32);
                uint32_t th[4], tl[4];
                ldsm_x4(th, vHi + bOff);
                ldsm_x4(tl, vHi + (KB_VLO - KB_VHI) + bOff);
                mma_bf16(oacc[2 * g],     af_hi, th);
                mma_bf16(oacc[2 * g],     af_hi, tl);
                mma_bf16(oacc[2 * g],     af_lo, th);
                mma_bf16(oacc[2 * g + 1], af_hi, th + 2);
                mma_bf16(oacc[2 * g + 1], af_hi, tl + 2);
                mma_bf16(oacc[2 * g + 1], af_lo, th + 2);
            }
        }

        __syncthreads();
        if (kt < NKT - 2) {
            const int k0n = (kt + 2) * KT;
            attn_cp_tile(sb, tid, krow0 + k0n, vbase, k0n, KB(cur));
            CP_COMMIT();
        }
    }

    float inv1 = 1.f / l1, inv2 = 1.f / l2;
    int qi1 = q0 + wid * 16 + r1;
    int qi2 = qi1 + 8;
#pragma unroll
    for (int n = 0; n < 8; n++) {
        int h = n * 8 + (lane & 3) * 2;
        if (qi1 < T_LEN) {
            float2 o = make_float2(oacc[n][0] * inv1, oacc[n][1] * inv1);
            *(float2*)&out[base + (size_t)qi1 * H_DIM + h] = o;
        }
        if (qi2 < T_LEN) {
            float2 o = make_float2(oacc[n][2] * inv2, oacc[n][3] * inv2);
            *(float2*)&out[base + (size_t)qi2 * H_DIM + h] = o;
        }
    }
}

// ---------------------------------------------------------------------------
extern "C" void kernel_launch(void* const* d_in, const int* in_sizes, int n_in,
                              void* d_out, int out_size)
{
    const float* x       = (const float*)d_in[0];
    const float* w_q     = (const float*)d_in[1];
    const float* w_k     = (const float*)d_in[2];
    const float* w_v     = (const float*)d_in[3];
    const float* q_gamma = (const float*)d_in[4];
    const float* q_beta  = (const float*)d_in[5];
    const float* k_gamma = (const float*)d_in[6];
    const float* k_beta  = (const float*)d_in[7];
    const float* w_sigma = (const float*)d_in[8];
    const float* b_sigma = (const float*)d_in[9];
    const float* w_alpha = (const float*)d_in[10];
    const float* b_alpha = (const float*)d_in[11];
    float* out = (float*)d_out;

    prep_w_kernel<<<(192 * E_DIM + 255) / 256, 256>>>(w_q, w_k, w_v);
    pad_kernel<<<(B_SZ * H_DIM * (TPAD - T_LEN) + 255) / 256, 256>>>();

    cudaFuncSetAttribute(qkv_mma_kernel, cudaFuncAttributeMaxDynamicSharedMemorySize, SM_TOTAL);
    qkv_mma_kernel<<<M_ROWS / 64, 256, SM_TOTAL>>>(x, q_gamma, q_beta, k_gamma, k_beta);

    cudaFuncSetAttribute(attn_mma_kernel, cudaFuncAttributeMaxDynamicSharedMemorySize, A_TOTAL);
    dim3 grid2((T_LEN + QT - 1) / QT, B_SZ);
    attn_mma_kernel<<<grid2, 128, A_TOTAL>>>(w_sigma, b_sigma, w_alpha, b_alpha, out);
}